// round 7
// baseline (speedup 1.0000x reference)
#include <cuda_runtime.h>
#include <cuda_fp16.h>
#include <cstdint>

// PLRNN step via mma.sync fp16 with FP16 ACCUMULATORS (rate experiment),
// promoted to fp32 registers after every K=64 chunk (bounded rounding error).
// cp.async 3-stage pipeline, K-chunk 64, SW128-style swizzle.
//   prepass: convert Z,W1,W2,S,C to fp16
//   GEMM1:   H  = relu(Zh @ W1h^T + h1) -> fp16              [8192,4096]
//   GEMM2:   out = A*z + Hh @ W2h^T + h2 + Sh @ Ch^T         [8192,1024] fp32

#define NT 128
#define BM 128
#define BN 128
#define BKH 64            // K halves per chunk (128 B per row)
#define DB 8192
#define DZv 1024
#define DHv 4096
#define DSv 64

static __device__ __align__(256) __half g_Hh [(size_t)DB * DHv];
static __device__ __align__(256) __half g_Zh [(size_t)DB * DZv];
static __device__ __align__(256) __half g_W1h[(size_t)DHv * DZv];
static __device__ __align__(256) __half g_W2h[(size_t)DZv * DHv];
static __device__ __align__(256) __half g_Sh [(size_t)DB * DSv];
static __device__ __align__(256) __half g_Ch [(size_t)DZv * DSv];

#define TILEB  16384              // 128 rows x 128 B
#define STAGEB (2 * TILEB)
#define SMEM_SZ (3 * STAGEB)      // 98304

__device__ __forceinline__ uint32_t smem_u32(const void* p) {
    uint32_t a;
    asm("{ .reg .u64 t; cvta.to.shared.u64 t, %1; cvt.u32.u64 %0, t; }" : "=r"(a) : "l"(p));
    return a;
}
__device__ __forceinline__ void cp16(uint32_t s, const void* g) {
    asm volatile("cp.async.cg.shared.global [%0], [%1], 16;" :: "r"(s), "l"(g));
}
#define CP_COMMIT() asm volatile("cp.async.commit_group;" ::: "memory")
#define CP_WAIT(n)  asm volatile("cp.async.wait_group %0;" :: "n"(n) : "memory")

__device__ __forceinline__ void ldsm4(uint32_t (&r)[4], uint32_t a) {
    asm volatile("ldmatrix.sync.aligned.m8n8.x4.shared.b16 {%0,%1,%2,%3}, [%4];"
        : "=r"(r[0]), "=r"(r[1]), "=r"(r[2]), "=r"(r[3]) : "r"(a));
}
// fp16-accumulate mma: D (f16x2 x2 regs) = A*B + D
__device__ __forceinline__ void mma16h(uint32_t (&d)[2], const uint32_t (&a)[4],
                                       uint32_t b0, uint32_t b1) {
    asm volatile("mma.sync.aligned.m16n8k16.row.col.f16.f16.f16.f16 "
        "{%0,%1}, {%2,%3,%4,%5}, {%6,%7}, {%0,%1};"
        : "+r"(d[0]), "+r"(d[1])
        : "r"(a[0]), "r"(a[1]), "r"(a[2]), "r"(a[3]), "r"(b0), "r"(b1));
}

// ---------------- prepass: fp32 -> fp16 ----------------
__global__ void k_prep(const float* __restrict__ z, const float* __restrict__ w1,
                       const float* __restrict__ w2, const float* __restrict__ s,
                       const float* __restrict__ c) {
    const float* src; __half* dst; size_t n8;
    switch (blockIdx.y) {
        case 0:  src = z;  dst = g_Zh;  n8 = (size_t)DB * DZv / 8;  break;
        case 1:  src = w1; dst = g_W1h; n8 = (size_t)DHv * DZv / 8; break;
        case 2:  src = w2; dst = g_W2h; n8 = (size_t)DZv * DHv / 8; break;
        case 3:  src = s;  dst = g_Sh;  n8 = (size_t)DB * DSv / 8;  break;
        default: src = c;  dst = g_Ch;  n8 = (size_t)DZv * DSv / 8; break;
    }
    size_t stride = (size_t)gridDim.x * blockDim.x;
    for (size_t i = (size_t)blockIdx.x * blockDim.x + threadIdx.x; i < n8; i += stride) {
        float4 v0 = reinterpret_cast<const float4*>(src)[2 * i];
        float4 v1 = reinterpret_cast<const float4*>(src)[2 * i + 1];
        __half2 h0 = __floats2half2_rn(v0.x, v0.y);
        __half2 h1 = __floats2half2_rn(v0.z, v0.w);
        __half2 h2 = __floats2half2_rn(v1.x, v1.y);
        __half2 h3 = __floats2half2_rn(v1.z, v1.w);
        uint4 o;
        o.x = *reinterpret_cast<uint32_t*>(&h0);
        o.y = *reinterpret_cast<uint32_t*>(&h1);
        o.z = *reinterpret_cast<uint32_t*>(&h2);
        o.w = *reinterpret_cast<uint32_t*>(&h3);
        reinterpret_cast<uint4*>(dst)[i] = o;
    }
}

// ---------------- fp16 mma GEMM (MODE 0: GEMM1, MODE 1: GEMM2) ----------------
template <int MODE>
__global__ void __launch_bounds__(NT, 2)
k_mma(const float* __restrict__ bias, const float* __restrict__ Avec,
      const float* __restrict__ Zorig, float* __restrict__ out) {
    extern __shared__ char smc[];
    const uint32_t smb = smem_u32(smc);
    constexpr int KBIG = (MODE == 0) ? DZv : DHv;
    constexpr int NCB  = KBIG / BKH;
    constexpr int NC   = (MODE == 0) ? NCB : NCB + 1;   // GEMM2: +1 chunk = S@C^T (K=64)
    const __half* gA = (MODE == 0) ? g_Zh  : g_Hh;
    const __half* gB = (MODE == 0) ? g_W1h : g_W2h;

    const int tid = threadIdx.x, lane = tid & 31, wid = tid >> 5;
    const int wm = wid & 1, wn = wid >> 1;           // 2x2 warps, 64x64 each
    const int bm = blockIdx.y * BM, bn = blockIdx.x * BN;

    // cp.async loader: thread -> (row residue 0..15, 16B chunk 0..7)
    const int lrow = tid >> 3;
    const int lc   = tid & 7;

    // ldmatrix lane constants
    const int rA  = lane & 15;
    const int cA  = lane >> 4;
    const int rB  = (lane & 7) + ((lane >> 4) & 1) * 8;
    const int cB  = (lane >> 3) & 1;

    float acc[4][8][4];
#pragma unroll
    for (int i = 0; i < 4; i++)
#pragma unroll
        for (int j = 0; j < 8; j++)
#pragma unroll
            for (int k = 0; k < 4; k++) acc[i][j][k] = 0.f;

    auto issue = [&](int cn, int stg) {
        const __half *pa, *pb; int ld, ko;
        if (MODE == 1 && cn >= NCB) { pa = g_Sh; pb = g_Ch; ld = DSv; ko = 0; }
        else                        { pa = gA;   pb = gB;   ld = KBIG; ko = cn * BKH; }
        uint32_t sA = smb + stg * STAGEB;
        uint32_t sB = sA + TILEB;
#pragma unroll
        for (int i = 0; i < 8; i++) {
            int row = lrow + 16 * i;
            uint32_t so = row * 128 + ((lc ^ (row & 7)) << 4);
            cp16(sA + so, pa + (size_t)(bm + row) * ld + ko + lc * 8);
            cp16(sB + so, pb + (size_t)(bn + row) * ld + ko + lc * 8);
        }
    };

    auto ldfrag = [&](int stg, int ks, uint32_t (&af)[4][4], uint32_t (&bf)[8][2]) {
        uint32_t sA = smb + stg * STAGEB;
        uint32_t sB = sA + TILEB;
#pragma unroll
        for (int mt = 0; mt < 4; mt++) {
            int r = wm * 64 + mt * 16 + rA;
            int c = 2 * ks + cA;
            ldsm4(af[mt], sA + r * 128 + ((c ^ (r & 7)) << 4));
        }
#pragma unroll
        for (int np = 0; np < 4; np++) {
            int r = wn * 64 + np * 16 + rB;
            int c = 2 * ks + cB;
            uint32_t t[4];
            ldsm4(t, sB + r * 128 + ((c ^ (r & 7)) << 4));
            bf[2 * np][0] = t[0];     bf[2 * np][1] = t[1];
            bf[2 * np + 1][0] = t[2]; bf[2 * np + 1][1] = t[3];
        }
    };

    // ---- 3-stage cp.async pipeline ----
    issue(0, 0); CP_COMMIT();
    issue(1, 1); CP_COMMIT();
#pragma unroll 1
    for (int c = 0; c < NC; c++) {
        if (c + 1 < NC) { CP_WAIT(1); } else { CP_WAIT(0); }
        __syncthreads();
        if (c + 2 < NC) { issue(c + 2, (c + 2) % 3); CP_COMMIT(); }

        const int stg = c % 3;
        // fp16 accumulators for this chunk (K=64), zero-initialized
        uint32_t hacc[4][8][2];
#pragma unroll
        for (int mt = 0; mt < 4; mt++)
#pragma unroll
            for (int nt = 0; nt < 8; nt++) { hacc[mt][nt][0] = 0u; hacc[mt][nt][1] = 0u; }

        uint32_t af[4][4], bf[8][2];
#pragma unroll
        for (int ks = 0; ks < 4; ks++) {
            ldfrag(stg, ks, af, bf);
#pragma unroll
            for (int mt = 0; mt < 4; mt++)
#pragma unroll
                for (int nt = 0; nt < 8; nt++)
                    mma16h(hacc[mt][nt], af[mt], bf[nt][0], bf[nt][1]);
        }

        // promote chunk partial sums to fp32
#pragma unroll
        for (int mt = 0; mt < 4; mt++)
#pragma unroll
            for (int nt = 0; nt < 8; nt++) {
                float2 lo = __half22float2(*reinterpret_cast<__half2*>(&hacc[mt][nt][0]));
                float2 hi = __half22float2(*reinterpret_cast<__half2*>(&hacc[mt][nt][1]));
                acc[mt][nt][0] += lo.x; acc[mt][nt][1] += lo.y;
                acc[mt][nt][2] += hi.x; acc[mt][nt][3] += hi.y;
            }
    }

    // ---- epilogue ----
    const int r0 = lane >> 2, cp2 = (lane & 3) * 2;
#pragma unroll
    for (int mt = 0; mt < 4; mt++) {
        const int row = bm + wm * 64 + mt * 16 + r0;
#pragma unroll
        for (int nt = 0; nt < 8; nt++) {
            const int col = bn + wn * 64 + nt * 8 + cp2;
            const float b0 = __ldg(bias + col), b1 = __ldg(bias + col + 1);
            if (MODE == 0) {
                __half2 v0 = __floats2half2_rn(fmaxf(acc[mt][nt][0] + b0, 0.f),
                                               fmaxf(acc[mt][nt][1] + b1, 0.f));
                __half2 v1 = __floats2half2_rn(fmaxf(acc[mt][nt][2] + b0, 0.f),
                                               fmaxf(acc[mt][nt][3] + b1, 0.f));
                *reinterpret_cast<__half2*>(g_Hh + (size_t)row * DHv + col) = v0;
                *reinterpret_cast<__half2*>(g_Hh + (size_t)(row + 8) * DHv + col) = v1;
            } else {
                const float a0 = __ldg(Avec + col), a1 = __ldg(Avec + col + 1);
                float2 z0 = *reinterpret_cast<const float2*>(Zorig + (size_t)row * DZv + col);
                float2 z1 = *reinterpret_cast<const float2*>(Zorig + (size_t)(row + 8) * DZv + col);
                float2 v0 = make_float2(acc[mt][nt][0] + a0 * z0.x + b0,
                                        acc[mt][nt][1] + a1 * z0.y + b1);
                float2 v1 = make_float2(acc[mt][nt][2] + a0 * z1.x + b0,
                                        acc[mt][nt][3] + a1 * z1.y + b1);
                *reinterpret_cast<float2*>(out + (size_t)row * DZv + col) = v0;
                *reinterpret_cast<float2*>(out + (size_t)(row + 8) * DZv + col) = v1;
            }
        }
    }
}

extern "C" void kernel_launch(void* const* d_in, const int* in_sizes, int n_in,
                              void* d_out, int out_size) {
    // metadata order: z, s, A, W1, W2, h1, h2, C
    const float* z  = (const float*)d_in[0];
    const float* s  = (const float*)d_in[1];
    const float* A  = (const float*)d_in[2];
    const float* W1 = (const float*)d_in[3];
    const float* W2 = (const float*)d_in[4];
    const float* h1 = (const float*)d_in[5];
    const float* h2 = (const float*)d_in[6];
    const float* C  = (const float*)d_in[7];
    float* out = (float*)d_out;
    (void)in_sizes; (void)n_in; (void)out_size;

    cudaFuncSetAttribute(k_mma<0>, cudaFuncAttributeMaxDynamicSharedMemorySize, SMEM_SZ);
    cudaFuncSetAttribute(k_mma<1>, cudaFuncAttributeMaxDynamicSharedMemorySize, SMEM_SZ);

    k_prep<<<dim3(1024, 5), 256>>>(z, W1, W2, s, C);
    k_mma<0><<<dim3(DHv / BN, DB / BM), NT, SMEM_SZ>>>(h1, nullptr, nullptr, nullptr);
    k_mma<1><<<dim3(DZv / BN, DB / BM), NT, SMEM_SZ>>>(h2, A, z, out);
}

// round 11
// speedup vs baseline: 1.2850x; 1.2850x over previous
#include <cuda_runtime.h>
#include <cuda_fp16.h>
#include <cstdint>

// PLRNN step, fp16 mma.sync m16n8k16 (fp32 accum), cp.async 3-stage pipeline,
// K-chunk 64, swizzled smem. GEMM1+GEMM2 FUSED in one kernel with per-row-strip
// dependency counters (G2 spins until its H strip is complete).
//   prepass: convert Z,W1,W2,S,C to fp16; zero strip counters
//   G1 bids [0,2048):   H = relu(Zh @ W1h^T + h1) -> fp16     [8192,4096]
//   G2 bids [2048,2560): out = A*z + Hh @ W2h^T + h2 + Sh @ Ch^T  [8192,1024]

#define NT 128
#define BM 128
#define BN 128
#define BKH 64
#define DB 8192
#define DZv 1024
#define DHv 4096
#define DSv 64
#define NG1 2048
#define NG2 512

static __device__ __align__(256) __half g_Hh [(size_t)DB * DHv];
static __device__ __align__(256) __half g_Zh [(size_t)DB * DZv];
static __device__ __align__(256) __half g_W1h[(size_t)DHv * DZv];
static __device__ __align__(256) __half g_W2h[(size_t)DZv * DHv];
static __device__ __align__(256) __half g_Sh [(size_t)DB * DSv];
static __device__ __align__(256) __half g_Ch [(size_t)DZv * DSv];
static __device__ unsigned g_cnt[DB / BM];   // H row-strip completion counters

#define TILEB  16384
#define STAGEB (2 * TILEB)
#define SMEM_SZ (3 * STAGEB)

__device__ __forceinline__ uint32_t smem_u32(const void* p) {
    uint32_t a;
    asm("{ .reg .u64 t; cvta.to.shared.u64 t, %1; cvt.u32.u64 %0, t; }" : "=r"(a) : "l"(p));
    return a;
}
__device__ __forceinline__ void cp16(uint32_t s, const void* g) {
    asm volatile("cp.async.cg.shared.global [%0], [%1], 16;" :: "r"(s), "l"(g));
}
#define CP_COMMIT() asm volatile("cp.async.commit_group;" ::: "memory")
#define CP_WAIT(n)  asm volatile("cp.async.wait_group %0;" :: "n"(n) : "memory")

__device__ __forceinline__ void ldsm4(uint32_t (&r)[4], uint32_t a) {
    asm volatile("ldmatrix.sync.aligned.m8n8.x4.shared.b16 {%0,%1,%2,%3}, [%4];"
        : "=r"(r[0]), "=r"(r[1]), "=r"(r[2]), "=r"(r[3]) : "r"(a));
}
__device__ __forceinline__ void mma16(float (&d)[4], const uint32_t (&a)[4],
                                      uint32_t b0, uint32_t b1) {
    asm volatile("mma.sync.aligned.m16n8k16.row.col.f32.f16.f16.f32 "
        "{%0,%1,%2,%3}, {%4,%5,%6,%7}, {%8,%9}, {%0,%1,%2,%3};"
        : "+f"(d[0]), "+f"(d[1]), "+f"(d[2]), "+f"(d[3])
        : "r"(a[0]), "r"(a[1]), "r"(a[2]), "r"(a[3]), "r"(b0), "r"(b1));
}

// ---------------- prepass: fp32 -> fp16, zero counters ----------------
__global__ void k_prep(const float* __restrict__ z, const float* __restrict__ w1,
                       const float* __restrict__ w2, const float* __restrict__ s,
                       const float* __restrict__ c) {
    if (blockIdx.y == 0 && blockIdx.x == 0 && threadIdx.x < DB / BM)
        g_cnt[threadIdx.x] = 0u;
    const float* src; __half* dst; size_t n8;
    switch (blockIdx.y) {
        case 0:  src = z;  dst = g_Zh;  n8 = (size_t)DB * DZv / 8;  break;
        case 1:  src = w1; dst = g_W1h; n8 = (size_t)DHv * DZv / 8; break;
        case 2:  src = w2; dst = g_W2h; n8 = (size_t)DZv * DHv / 8; break;
        case 3:  src = s;  dst = g_Sh;  n8 = (size_t)DB * DSv / 8;  break;
        default: src = c;  dst = g_Ch;  n8 = (size_t)DZv * DSv / 8; break;
    }
    size_t stride = (size_t)gridDim.x * blockDim.x;
    for (size_t i = (size_t)blockIdx.x * blockDim.x + threadIdx.x; i < n8; i += stride) {
        float4 v0 = reinterpret_cast<const float4*>(src)[2 * i];
        float4 v1 = reinterpret_cast<const float4*>(src)[2 * i + 1];
        __half2 h0 = __floats2half2_rn(v0.x, v0.y);
        __half2 h1 = __floats2half2_rn(v0.z, v0.w);
        __half2 h2 = __floats2half2_rn(v1.x, v1.y);
        __half2 h3 = __floats2half2_rn(v1.z, v1.w);
        uint4 o;
        o.x = *reinterpret_cast<uint32_t*>(&h0);
        o.y = *reinterpret_cast<uint32_t*>(&h1);
        o.z = *reinterpret_cast<uint32_t*>(&h2);
        o.w = *reinterpret_cast<uint32_t*>(&h3);
        reinterpret_cast<uint4*>(dst)[i] = o;
    }
}

// ---------------- GEMM body (MODE 0: G1, MODE 1: G2) ----------------
template <int MODE>
__device__ __forceinline__ void run_gemm(int bm, int bn,
        const float* __restrict__ bias, const float* __restrict__ Avec,
        const float* __restrict__ Zorig, float* __restrict__ out, char* smc) {
    const uint32_t smb = smem_u32(smc);
    // MODE 0: 16 chunks of Zh/W1h. MODE 1: chunk 0 = S@C^T, chunks 1..64 = H/W2.
    constexpr int NC = (MODE == 0) ? (DZv / BKH) : (DHv / BKH + 1);

    const int tid = threadIdx.x, lane = tid & 31, wid = tid >> 5;
    const int wm = wid & 1, wn = wid >> 1;
    const int lrow = tid >> 3, lc = tid & 7;
    const int rA = lane & 15, cA = lane >> 4;
    const int rB = (lane & 7) + ((lane >> 4) & 1) * 8, cB = (lane >> 3) & 1;

    float acc[4][8][4];
#pragma unroll
    for (int i = 0; i < 4; i++)
#pragma unroll
        for (int j = 0; j < 8; j++)
#pragma unroll
            for (int k = 0; k < 4; k++) acc[i][j][k] = 0.f;

    auto issue = [&](int cn, int stg) {
        const __half *pa, *pb; int ld, ko;
        if (MODE == 0)       { pa = g_Zh; pb = g_W1h; ld = DZv; ko = cn * BKH; }
        else if (cn == 0)    { pa = g_Sh; pb = g_Ch;  ld = DSv; ko = 0; }
        else                 { pa = g_Hh; pb = g_W2h; ld = DHv; ko = (cn - 1) * BKH; }
        uint32_t sA = smb + stg * STAGEB;
        uint32_t sB = sA + TILEB;
#pragma unroll
        for (int i = 0; i < 8; i++) {
            int row = lrow + 16 * i;
            uint32_t so = row * 128 + ((lc ^ (row & 7)) << 4);
            cp16(sA + so, pa + (size_t)(bm + row) * ld + ko + lc * 8);
            cp16(sB + so, pb + (size_t)(bn + row) * ld + ko + lc * 8);
        }
    };

    auto ldfrag = [&](int stg, int ks, uint32_t (&af)[4][4], uint32_t (&bf)[8][2]) {
        uint32_t sA = smb + stg * STAGEB;
        uint32_t sB = sA + TILEB;
#pragma unroll
        for (int mt = 0; mt < 4; mt++) {
            int r = wm * 64 + mt * 16 + rA;
            int c = 2 * ks + cA;
            ldsm4(af[mt], sA + r * 128 + ((c ^ (r & 7)) << 4));
        }
#pragma unroll
        for (int np = 0; np < 4; np++) {
            int r = wn * 64 + np * 16 + rB;
            int c = 2 * ks + cB;
            uint32_t t[4];
            ldsm4(t, sB + r * 128 + ((c ^ (r & 7)) << 4));
            bf[2 * np][0] = t[0];     bf[2 * np][1] = t[1];
            bf[2 * np + 1][0] = t[2]; bf[2 * np + 1][1] = t[3];
        }
    };

    // ---- pipeline prologue ----
    issue(0, 0); CP_COMMIT();
    if (MODE == 1) {
        // wait for this row strip of H (overlapped with the S@C^T cp.async)
        if (tid == 0) {
            unsigned v;
            do {
                asm volatile("ld.global.acquire.gpu.b32 %0, [%1];"
                             : "=r"(v) : "l"(g_cnt + (bm >> 7)) : "memory");
                if (v < DHv / BN) __nanosleep(100);
            } while (v < DHv / BN);
        }
        __syncthreads();
    }
    issue(1, 1); CP_COMMIT();

#pragma unroll 1
    for (int c = 0; c < NC; c++) {
        if (c + 1 < NC) { CP_WAIT(1); } else { CP_WAIT(0); }
        __syncthreads();
        if (c + 2 < NC) { issue(c + 2, (c + 2) % 3); CP_COMMIT(); }

        const int stg = c % 3;
        uint32_t af[2][4][4], bf[2][8][2];
        ldfrag(stg, 0, af[0], bf[0]);
#pragma unroll
        for (int ks = 0; ks < 4; ks++) {
            if (ks < 3) ldfrag(stg, ks + 1, af[(ks + 1) & 1], bf[(ks + 1) & 1]);
            const int cur = ks & 1;
#pragma unroll
            for (int mt = 0; mt < 4; mt++)
#pragma unroll
                for (int nt = 0; nt < 8; nt++)
                    mma16(acc[mt][nt], af[cur][mt], bf[cur][nt][0], bf[cur][nt][1]);
        }
    }

    // ---- epilogue ----
    const int r0 = lane >> 2, cp2 = (lane & 3) * 2;
#pragma unroll
    for (int mt = 0; mt < 4; mt++) {
        const int row = bm + wm * 64 + mt * 16 + r0;
#pragma unroll
        for (int nt = 0; nt < 8; nt++) {
            const int col = bn + wn * 64 + nt * 8 + cp2;
            const float b0 = __ldg(bias + col), b1 = __ldg(bias + col + 1);
            if (MODE == 0) {
                __half2 v0 = __floats2half2_rn(fmaxf(acc[mt][nt][0] + b0, 0.f),
                                               fmaxf(acc[mt][nt][1] + b1, 0.f));
                __half2 v1 = __floats2half2_rn(fmaxf(acc[mt][nt][2] + b0, 0.f),
                                               fmaxf(acc[mt][nt][3] + b1, 0.f));
                *reinterpret_cast<__half2*>(g_Hh + (size_t)row * DHv + col) = v0;
                *reinterpret_cast<__half2*>(g_Hh + (size_t)(row + 8) * DHv + col) = v1;
            } else {
                const float a0 = __ldg(Avec + col), a1 = __ldg(Avec + col + 1);
                float2 z0 = *reinterpret_cast<const float2*>(Zorig + (size_t)row * DZv + col);
                float2 z1 = *reinterpret_cast<const float2*>(Zorig + (size_t)(row + 8) * DZv + col);
                float2 v0 = make_float2(acc[mt][nt][0] + a0 * z0.x + b0,
                                        acc[mt][nt][1] + a1 * z0.y + b1);
                float2 v1 = make_float2(acc[mt][nt][2] + a0 * z1.x + b0,
                                        acc[mt][nt][3] + a1 * z1.y + b1);
                *reinterpret_cast<float2*>(out + (size_t)row * DZv + col) = v0;
                *reinterpret_cast<float2*>(out + (size_t)(row + 8) * DZv + col) = v1;
            }
        }
    }

    if (MODE == 0) {
        // publish this H tile: every thread fences its stores, then one arrive
        __threadfence();
        __syncthreads();
        if (tid == 0) atomicAdd(&g_cnt[bm >> 7], 1u);
    }
}

__global__ void __launch_bounds__(NT, 2)
k_fused(const float* __restrict__ h1, const float* __restrict__ h2,
        const float* __restrict__ Avec, const float* __restrict__ z,
        float* __restrict__ out) {
    extern __shared__ char smc[];
    const int bid = blockIdx.x;
    if (bid < NG1) {
        run_gemm<0>((bid >> 5) * BM, (bid & 31) * BN, h1, nullptr, nullptr, nullptr, smc);
    } else {
        const int t = bid - NG1;
        run_gemm<1>((t >> 3) * BM, (t & 7) * BN, h2, Avec, z, out, smc);
    }
}

extern "C" void kernel_launch(void* const* d_in, const int* in_sizes, int n_in,
                              void* d_out, int out_size) {
    // metadata order: z, s, A, W1, W2, h1, h2, C
    const float* z  = (const float*)d_in[0];
    const float* s  = (const float*)d_in[1];
    const float* A  = (const float*)d_in[2];
    const float* W1 = (const float*)d_in[3];
    const float* W2 = (const float*)d_in[4];
    const float* h1 = (const float*)d_in[5];
    const float* h2 = (const float*)d_in[6];
    const float* C  = (const float*)d_in[7];
    float* out = (float*)d_out;
    (void)in_sizes; (void)n_in; (void)out_size;

    cudaFuncSetAttribute(k_fused, cudaFuncAttributeMaxDynamicSharedMemorySize, SMEM_SZ);

    k_prep<<<dim3(1024, 5), 256>>>(z, W1, W2, s, C);
    k_fused<<<NG1 + NG2, NT, SMEM_SZ>>>(h1, h2, A, z, out);
}